// round 3
// baseline (speedup 1.0000x reference)
#include <cuda_runtime.h>
#include <cuda_bf16.h>

// Problem constants (fixed by setup_inputs)
constexpr int B = 4;
constexpr int D = 128;
constexpr int N = 100000;   // divisible by 32 (3125 tiles of 32)
constexpr int G = 16;
constexpr int V = G * G * G;  // 4096

// Scratch: sums in [B, V, D] layout (D contiguous -> red.v4 targets), counts [B, V]
__device__ __align__(16) float g_sums[(size_t)B * V * D];   // 8 MB
__device__ int g_counts[B * V];

__device__ __forceinline__ void red_add_v4(float* addr, float4 v) {
    asm volatile("red.global.add.v4.f32 [%0], {%1, %2, %3, %4};"
                 :: "l"(addr), "f"(v.x), "f"(v.y), "f"(v.z), "f"(v.w)
                 : "memory");
}

// ---------------------------------------------------------------------------
// K0: zero the accumulator state (must run every replay: graph re-executes)
// ---------------------------------------------------------------------------
__global__ void vox_zero_kernel() {
    int gid = blockIdx.x * blockDim.x + threadIdx.x;
    float4* p = reinterpret_cast<float4*>(g_sums);
    if (gid < (B * V * D) / 4) p[gid] = make_float4(0.f, 0.f, 0.f, 0.f);
    if (gid < B * V) g_counts[gid] = 0;
}

// ---------------------------------------------------------------------------
// K1: fused voxel-index + count + tiled feature scatter.
// Block = 128 threads, tile = 32 points x 128 channels.
//   Phase A (threads 0..31): compute voxel idx for the 32 points, count atomics.
//   Phase B (all): load features [d][n] coalesced into SMEM (transposed).
//   Phase C: warps iterate points; lanes span d in float4 chunks -> red.v4
//            into g_sums[b][v][4*lane .. 4*lane+3] (512B contiguous per warp).
// ---------------------------------------------------------------------------
__global__ __launch_bounds__(128) void vox_scatter_kernel(
    const float* __restrict__ features,   // [B, D, N]
    const float* __restrict__ xyz,        // [B, N, 3]
    const int*   __restrict__ mask)       // [B, N]
{
    __shared__ int s_vidx[32];
    __shared__ float4 s_f[32][33];        // [point][d/4], padded row (33 float4)

    const int b   = blockIdx.y;
    const int n0  = blockIdx.x * 32;
    const int tid = threadIdx.x;
    const int lane = tid & 31;
    const int w    = tid >> 5;

    // Phase A: voxel indices + counts (one lane per point)
    if (tid < 32) {
        const int n = n0 + tid;
        const float* p = xyz + ((long long)b * N + n) * 3;
        float x = p[0], y = p[1], z = p[2];
        int vx = min(max((int)(x * (float)G), 0), G - 1);
        int vy = min(max((int)(y * (float)G), 0), G - 1);
        int vz = min(max((int)(z * (float)G), 0), G - 1);
        int flat = (vz * G + vy) * G + vx;
        int m = mask[(long long)b * N + n];
        s_vidx[tid] = m ? flat : -1;
        if (m) atomicAdd(&g_counts[b * V + flat], 1);
    }

    // Phase B: coalesced feature tile load -> SMEM transposed
    float* sf = reinterpret_cast<float*>(s_f);        // float view, row stride 132
    const float* fb = features + (long long)b * D * N + n0;
    #pragma unroll 8
    for (int d = w; d < D; d += 4) {
        sf[lane * 132 + d] = fb[(long long)d * N + lane];
    }
    __syncthreads();

    // Phase C: vectorized scatter (warp-uniform mask skip)
    for (int p = w; p < 32; p += 4) {
        int v = s_vidx[p];
        if (v < 0) continue;
        float4 val = s_f[p][lane];
        red_add_v4(&g_sums[(((long long)b * V + v) << 7) + (lane << 2)], val);
    }
}

// ---------------------------------------------------------------------------
// K2: normalize by counts and transpose [B,V,D] -> [B,D,V].
// Block = 256 threads, tile = 32 voxels x 128 channels. Coalesced both sides.
// ---------------------------------------------------------------------------
__global__ __launch_bounds__(256) void vox_finalize_kernel(float* __restrict__ out)
{
    __shared__ float sT[128 * 33];   // [d][vv], padded
    __shared__ float s_inv[32];

    const int b   = blockIdx.y;
    const int v0  = blockIdx.x * 32;
    const int tid = threadIdx.x;

    if (tid < 32) {
        int c = g_counts[b * V + v0 + tid];
        s_inv[tid] = 1.0f / (float)max(c, 1);
    }
    __syncthreads();

    const float* src = g_sums + (((long long)b * V + v0) << 7);
    #pragma unroll
    for (int it = 0; it < 16; it++) {
        int e  = it * 256 + tid;        // 0..4095
        int vv = e >> 7;                // voxel within tile
        int d  = e & 127;               // channel
        sT[d * 33 + vv] = src[e] * s_inv[vv];
    }
    __syncthreads();

    float* dst = out + (long long)b * D * V + v0;
    #pragma unroll
    for (int it = 0; it < 16; it++) {
        int e  = it * 256 + tid;
        int d  = e >> 5;
        int vv = e & 31;
        dst[(long long)d * V + vv] = sT[d * 33 + vv];
    }
}

// ---------------------------------------------------------------------------
extern "C" void kernel_launch(void* const* d_in, const int* in_sizes, int n_in,
                              void* d_out, int out_size)
{
    const float* features = (const float*)d_in[0];   // [B, D, N]
    const float* xyz      = (const float*)d_in[1];   // [B, N, 3]
    const int*   mask     = (const int*)d_in[2];     // [B, N]
    float* out = (float*)d_out;                      // [B, D, V]

    // K0: zero accumulators (524288 float4 elements)
    {
        int total = (B * V * D) / 4;                 // 524288
        vox_zero_kernel<<<(total + 255) / 256, 256>>>();
    }
    // K1: scatter
    {
        dim3 grid(N / 32, B);                        // 3125 x 4
        vox_scatter_kernel<<<grid, 128>>>(features, xyz, mask);
    }
    // K2: normalize + transpose
    {
        dim3 grid(V / 32, B);                        // 128 x 4
        vox_finalize_kernel<<<grid, 256>>>(out);
    }
}

// round 5
// speedup vs baseline: 1.0005x; 1.0005x over previous
#include <cuda_runtime.h>
#include <cuda_bf16.h>

// Problem constants (fixed by setup_inputs)
constexpr int B = 4;
constexpr int D = 128;
constexpr int N = 100000;   // divisible by 32 (3125 tiles of 32) and by 4
constexpr int G = 16;
constexpr int V = G * G * G;  // 4096

// Scratch: sums in [B, V, D] layout (D contiguous -> red.v4 targets), counts [B, V].
// Zero-initialized at module load; K2 restores the all-zero invariant every
// invocation, so no separate zeroing kernel is needed.
__device__ __align__(16) float g_sums[(size_t)B * V * D];   // 8 MB
__device__ int g_counts[B * V];

__device__ __forceinline__ void red_add_v4(float* addr, float4 v) {
    asm volatile("red.global.add.v4.f32 [%0], {%1, %2, %3, %4};"
                 :: "l"(addr), "f"(v.x), "f"(v.y), "f"(v.z), "f"(v.w)
                 : "memory");
}

// ---------------------------------------------------------------------------
// K1: fused voxel-index + count + tiled feature scatter.
// Block = 128 threads (4 warps), tile = 32 points x 128 channels.
//   Phase A (threads 0..31): voxel idx for the 32 points + count atomics.
//   Phase B: LDG.128 loads — each warp instruction covers 4 d-rows x 32 points
//            (lanes 0-7 -> row d, 8-15 -> d+1, ...; 4x 128B coalesced segs).
//            Scalar STS into [point][132] padded rows (4-way, floor pattern).
//   Phase C: warps iterate points; lanes span d as float4 (conflict-free
//            LDS.128) -> red.v4 into g_sums[b][v][4*lane..] (512B/warp).
// ---------------------------------------------------------------------------
__global__ __launch_bounds__(128) void vox_scatter_kernel(
    const float* __restrict__ features,   // [B, D, N]
    const float* __restrict__ xyz,        // [B, N, 3]
    const int*   __restrict__ mask)       // [B, N]
{
    __shared__ int s_vidx[32];
    __shared__ float s_f[32 * 132];       // [point][d], padded row = 132 floats

    const int b    = blockIdx.y;
    const int n0   = blockIdx.x * 32;
    const int tid  = threadIdx.x;
    const int lane = tid & 31;
    const int w    = tid >> 5;

    // Phase A: voxel indices + counts (one lane per point)
    if (tid < 32) {
        const int n = n0 + tid;
        const float* p = xyz + ((long long)b * N + n) * 3;
        float x = p[0], y = p[1], z = p[2];
        int vx = min(max((int)(x * (float)G), 0), G - 1);
        int vy = min(max((int)(y * (float)G), 0), G - 1);
        int vz = min(max((int)(z * (float)G), 0), G - 1);
        int flat = (vz * G + vy) * G + vx;
        int m = mask[(long long)b * N + n];
        s_vidx[tid] = m ? flat : -1;
        if (m) atomicAdd(&g_counts[b * V + flat], 1);
    }

    // Phase B: vectorized feature tile load -> SMEM transpose
    const float4* fb4 = reinterpret_cast<const float4*>(features + (long long)b * D * N);
    const int Nq  = N >> 2;               // 25000 float4 per row
    const int nq0 = n0 >> 2;
    const int sub = lane >> 3;            // row offset within quad (0..3)
    const int q   = lane & 7;             // float4 slot within 32 points (0..7)
    #pragma unroll
    for (int it = 0; it < 8; it++) {
        const int d = it * 16 + w * 4 + sub;          // covers 0..127 uniquely
        const float4 v = fb4[(long long)d * Nq + nq0 + q];
        const int p = q << 2;
        s_f[(p + 0) * 132 + d] = v.x;
        s_f[(p + 1) * 132 + d] = v.y;
        s_f[(p + 2) * 132 + d] = v.z;
        s_f[(p + 3) * 132 + d] = v.w;
    }
    __syncthreads();

    // Phase C: vectorized scatter (warp-uniform mask skip)
    for (int p = w; p < 32; p += 4) {
        const int v = s_vidx[p];
        if (v < 0) continue;
        const float4 val = reinterpret_cast<const float4*>(s_f + p * 132)[lane];
        red_add_v4(&g_sums[(((long long)b * V + v) << 7) + (lane << 2)], val);
    }
}

// ---------------------------------------------------------------------------
// K2: normalize by counts, transpose [B,V,D] -> [B,D,V], and restore the
// all-zero scratch invariant (sums + counts) for the next graph replay.
// Block = 256 threads, tile = 32 voxels x 128 channels. Coalesced both sides.
// ---------------------------------------------------------------------------
__global__ __launch_bounds__(256) void vox_finalize_kernel(float* __restrict__ out)
{
    __shared__ float sT[128 * 33];   // [d][vv], padded
    __shared__ float s_inv[32];

    const int b   = blockIdx.y;
    const int v0  = blockIdx.x * 32;
    const int tid = threadIdx.x;

    if (tid < 32) {
        int c = g_counts[b * V + v0 + tid];
        s_inv[tid] = 1.0f / (float)max(c, 1);
    }
    __syncthreads();

    float* src = g_sums + (((long long)b * V + v0) << 7);
    #pragma unroll
    for (int it = 0; it < 16; it++) {
        int e  = it * 256 + tid;        // 0..4095
        int vv = e >> 7;                // voxel within tile
        int d  = e & 127;               // channel
        sT[d * 33 + vv] = src[e] * s_inv[vv];
    }
    __syncthreads();                    // all reads of src / counts done

    // Restore scratch to zero for the next replay (L2-resident, cheap)
    {
        float4* src4 = reinterpret_cast<float4*>(src);
        const float4 z = make_float4(0.f, 0.f, 0.f, 0.f);
        #pragma unroll
        for (int it = 0; it < 4; it++)
            src4[it * 256 + tid] = z;   // 1024 float4 = 4096 floats
        if (tid < 32) g_counts[b * V + v0 + tid] = 0;
    }

    float* dst = out + (long long)b * D * V + v0;
    #pragma unroll
    for (int it = 0; it < 16; it++) {
        int e  = it * 256 + tid;
        int d  = e >> 5;
        int vv = e & 31;
        dst[(long long)d * V + vv] = sT[d * 33 + vv];
    }
}

// ---------------------------------------------------------------------------
extern "C" void kernel_launch(void* const* d_in, const int* in_sizes, int n_in,
                              void* d_out, int out_size)
{
    const float* features = (const float*)d_in[0];   // [B, D, N]
    const float* xyz      = (const float*)d_in[1];   // [B, N, 3]
    const int*   mask     = (const int*)d_in[2];     // [B, N]
    float* out = (float*)d_out;                      // [B, D, V]

    // K1: scatter (scratch is guaranteed zero: module init + K2 restore)
    {
        dim3 grid(N / 32, B);                        // 3125 x 4
        vox_scatter_kernel<<<grid, 128>>>(features, xyz, mask);
    }
    // K2: normalize + transpose + re-zero scratch
    {
        dim3 grid(V / 32, B);                        // 128 x 4
        vox_finalize_kernel<<<grid, 256>>>(out);
    }
}